// round 2
// baseline (speedup 1.0000x reference)
#include <cuda_runtime.h>
#include <cuda_bf16.h>
#include <cstdint>

// LJ constants (match reference)
#define EPSILON 1.0f
// SHIFT = 4*eps*((sigma/cutoff)^12 - (sigma/cutoff)^6), sigma=1, cutoff=5
#define SHIFT_F (4.0f * (1.0f/244140625.0f - 1.0f/15625.0f))

__global__ void lj_zero_kernel(float* __restrict__ out, int n) {
    int i = blockIdx.x * blockDim.x + threadIdx.x;
    if (i < n) out[i] = 0.0f;
}

__global__ void __launch_bounds__(256)
lj_edge_kernel(const float* __restrict__ dist,
               const int* __restrict__ atom_a,
               const int* __restrict__ atom_b,
               float* __restrict__ out,
               int n_edges) {
    int i = blockIdx.x * blockDim.x + threadIdx.x;
    if (i >= n_edges) return;

    // [E,3] row-major: warp reads 384 contiguous bytes = fully coalesced.
    float x = dist[3 * i + 0];
    float y = dist[3 * i + 1];
    float z = dist[3 * i + 2];

    float r2   = fmaf(x, x, fmaf(y, y, z * z));
    float inv2 = 1.0f / r2;                 // only even powers -> no sqrt needed
    float sr6  = inv2 * inv2 * inv2;        // (sigma/r)^6, sigma=1
    float e    = 4.0f * EPSILON * fmaf(sr6, sr6, -sr6) - SHIFT_F;
    float h    = 0.5f * e;

    int ia = atom_a[i];
    int ib = atom_b[i];

    // fire-and-forget: compiles to RED.ADD (no return value)
    atomicAdd(out + ia, h);
    atomicAdd(out + ib, h);
}

extern "C" void kernel_launch(void* const* d_in, const int* in_sizes, int n_in,
                              void* d_out, int out_size) {
    const float* dist   = (const float*)d_in[0];
    const int*   atom_a = (const int*)d_in[1];   // JAX x64-disabled: randint -> int32
    const int*   atom_b = (const int*)d_in[2];
    float* out = (float*)d_out;

    int n_edges = in_sizes[1];     // first_atom element count = E
    int n_atoms = out_size;        // output is [n_atoms] f32

    // d_out poisoned to 0xAA — zero before accumulation.
    {
        int threads = 256;
        int blocks = (n_atoms + threads - 1) / threads;
        lj_zero_kernel<<<blocks, threads>>>(out, n_atoms);
    }
    {
        int threads = 256;
        int blocks = (n_edges + threads - 1) / threads;
        lj_edge_kernel<<<blocks, threads>>>(dist, atom_a, atom_b, out, n_edges);
    }
}